// round 2
// baseline (speedup 1.0000x reference)
#include <cuda_runtime.h>

#define Bb   8
#define Nn   4096
#define Mm   2048
#define DIN  256
#define DOUT 128

// Scratch (allocation-free rule: __device__ globals)
__device__ float g_Q [Bb*Mm*DOUT];        // [b][m][e]
__device__ float g_Kt[Bb*DOUT*Mm];        // [b][e][n]  (transposed K)
__device__ float g_V [Bb*Mm*DOUT];        // [b][m][e]

// ---------------------------------------------------------------------------
// Kernel 1: gather + Q/K/V projections.
// 128 threads, 32-row tile. smem: gS[32][256] (32KB) + Ws[64][128] (32KB).
// Thread (tx=tid%32 -> 4 cols, ty=tid/32 -> 8 rows): 8x4 register tile.
// ---------------------------------------------------------------------------
__global__ __launch_bounds__(128)
void proj_kernel(const float* __restrict__ Y, const int* __restrict__ idx,
                 const float* __restrict__ Wq, const float* __restrict__ bq,
                 const float* __restrict__ Wk, const float* __restrict__ bk,
                 const float* __restrict__ Wv, const float* __restrict__ bv)
{
    extern __shared__ float sm[];
    float* gS = sm;             // 32*256
    float* Ws = sm + 32*256;    // 64*128
    __shared__ int idxs[32];

    const int tid  = threadIdx.x;
    const int row0 = blockIdx.x * 32;
    const int b    = row0 / Mm;
    const int m0   = row0 % Mm;

    if (tid < 32) idxs[tid] = idx[b*Mm + m0 + tid];
    __syncthreads();

    // gather 32 rows x 256 floats (float4)
    for (int i = tid; i < 32*64; i += 128) {
        int r = i >> 6, c4 = i & 63;
        const float4* yp = reinterpret_cast<const float4*>(
            Y + ((size_t)b*Nn + idxs[r]) * DIN);
        reinterpret_cast<float4*>(gS + r*DIN)[c4] = yp[c4];
    }
    // (covered by the sync at the top of the first k-chunk)

    const int tx = tid & 31;
    const int ty = tid >> 5;
    const int c0 = tx * 4;

    const float* Wlist[3] = {Wq, Wk, Wv};
    const float* blist[3] = {bq, bk, bv};

    #pragma unroll 1
    for (int wsel = 0; wsel < 3; ++wsel) {
        const float* W = Wlist[wsel];
        float acc[8][4];
        {
            float b0v = blist[wsel][c0+0], b1v = blist[wsel][c0+1];
            float b2v = blist[wsel][c0+2], b3v = blist[wsel][c0+3];
            #pragma unroll
            for (int r = 0; r < 8; r++) {
                acc[r][0]=b0v; acc[r][1]=b1v; acc[r][2]=b2v; acc[r][3]=b3v;
            }
        }

        #pragma unroll 1
        for (int k0 = 0; k0 < DIN; k0 += 64) {
            __syncthreads();     // protects Ws reuse + (first iter) gather done
            for (int i = tid; i < 64*32; i += 128) {
                int kk = i >> 5, c4 = i & 31;
                reinterpret_cast<float4*>(Ws + kk*DOUT)[c4] =
                    reinterpret_cast<const float4*>(W + (size_t)(k0+kk)*DOUT)[c4];
            }
            __syncthreads();
            #pragma unroll 4
            for (int kk = 0; kk < 64; kk++) {
                float4 w4 = reinterpret_cast<float4*>(Ws + kk*DOUT)[tx];
                #pragma unroll
                for (int r = 0; r < 8; r++) {
                    float gv = gS[(ty*8+r)*DIN + k0 + kk];  // warp broadcast
                    acc[r][0] = fmaf(gv, w4.x, acc[r][0]);
                    acc[r][1] = fmaf(gv, w4.y, acc[r][1]);
                    acc[r][2] = fmaf(gv, w4.z, acc[r][2]);
                    acc[r][3] = fmaf(gv, w4.w, acc[r][3]);
                }
            }
        }

        if (wsel == 0) {
            #pragma unroll
            for (int r = 0; r < 8; r++) {
                int m = m0 + ty*8 + r;
                float4 v4 = make_float4(acc[r][0],acc[r][1],acc[r][2],acc[r][3]);
                reinterpret_cast<float4*>(g_Q + ((size_t)b*Mm + m)*DOUT)[tx] = v4;
            }
        } else if (wsel == 1) {
            // transposed store: g_Kt[b][e][n]
            #pragma unroll
            for (int r = 0; r < 8; r++) {
                int m = m0 + ty*8 + r;
                #pragma unroll
                for (int j = 0; j < 4; j++)
                    g_Kt[((size_t)b*DOUT + c0 + j)*Mm + m] = acc[r][j];
            }
        } else {
            #pragma unroll
            for (int r = 0; r < 8; r++) {
                int m = m0 + ty*8 + r;
                float4 v4 = make_float4(fmaxf(acc[r][0],0.f), fmaxf(acc[r][1],0.f),
                                        fmaxf(acc[r][2],0.f), fmaxf(acc[r][3],0.f));
                reinterpret_cast<float4*>(g_V + ((size_t)b*Mm + m)*DOUT)[tx] = v4;
            }
        }
    }
}

// ---------------------------------------------------------------------------
// Kernel 2: fused attention for 16 query rows of one batch.
// 256 threads. smem: S[16][2048] 128KB + Qs/AVs[16][128] 8KB + Ts[128][128] 64KB.
// Phase 1: S = Q Kt / 16 (chunks of 128 keys).
// Softmax in smem, att written to gmem.
// Phase 2: AV = S V (chunks of 128 value rows), then dual-l2norm epilogue.
// ---------------------------------------------------------------------------
__global__ __launch_bounds__(256, 1)
void attn_kernel(float* __restrict__ out, float* __restrict__ att)
{
    extern __shared__ float sm[];
    float* S  = sm;                   // 16*2048
    float* Qs = sm + 16*2048;         // 16*128, reused as AVs in epilogue
    float* Ts = Qs + 16*DOUT;         // 128*128 (K chunk / V chunk)

    const int tid = threadIdx.x;      // 256
    const int b   = blockIdx.y;
    const int m0  = blockIdx.x * 16;

    // load Q tile
    for (int i = tid; i < 16*32; i += 256) {
        int r = i >> 5, c4 = i & 31;
        reinterpret_cast<float4*>(Qs + r*DOUT)[c4] =
            reinterpret_cast<const float4*>(g_Q + ((size_t)b*Mm + m0 + r)*DOUT)[c4];
    }

    const int cg = tid & 63;          // 64 col-groups of 2 (contiguous per lane)
    const int rg = tid >> 6;          // 4 row-groups of 4 (constant within warp)
    const int c0 = cg * 2;

    // ---------------- phase 1: S = Q K^T * (1/16) ----------------
    #pragma unroll 1
    for (int n0 = 0; n0 < Mm; n0 += 128) {
        __syncthreads();
        // stage KsT[k][n] (128 x 128): gmem coalesced, smem conflict-free
        for (int i = tid; i < 128*32; i += 256) {
            int k = i >> 5, c4 = i & 31;
            reinterpret_cast<float4*>(Ts + k*128)[c4] =
                reinterpret_cast<const float4*>(
                    g_Kt + ((size_t)b*DOUT + k)*Mm + n0)[c4];
        }
        __syncthreads();
        float acc[4][2] = {};
        #pragma unroll 4
        for (int k = 0; k < DOUT; k++) {
            float2 k2 = reinterpret_cast<float2*>(Ts + k*128)[cg];
            #pragma unroll
            for (int i = 0; i < 4; i++) {
                float qv = Qs[(rg*4 + i)*DOUT + k];   // warp broadcast
                acc[i][0] = fmaf(qv, k2.x, acc[i][0]);
                acc[i][1] = fmaf(qv, k2.y, acc[i][1]);
            }
        }
        const float scale = 0.0625f;  // 1/sqrt(256)
        #pragma unroll
        for (int i = 0; i < 4; i++) {
            S[(rg*4+i)*Mm + n0 + c0    ] = acc[i][0] * scale;
            S[(rg*4+i)*Mm + n0 + c0 + 1] = acc[i][1] * scale;
        }
    }
    __syncthreads();

    // ---------------- softmax (warp w owns rows 2w, 2w+1) ----------------
    {
        const int w = tid >> 5, lane = tid & 31;
        #pragma unroll 1
        for (int rr = 0; rr < 2; rr++) {
            int r = w*2 + rr;
            float* Sr = S + r*Mm;
            float mx = -1e30f;
            for (int n = lane; n < Mm; n += 32) mx = fmaxf(mx, Sr[n]);
            #pragma unroll
            for (int o = 16; o > 0; o >>= 1)
                mx = fmaxf(mx, __shfl_xor_sync(0xffffffffu, mx, o));
            float sum = 0.f;
            for (int n = lane; n < Mm; n += 32) {
                float e = __expf(Sr[n] - mx);
                Sr[n] = e;
                sum += e;
            }
            #pragma unroll
            for (int o = 16; o > 0; o >>= 1)
                sum += __shfl_xor_sync(0xffffffffu, sum, o);
            float inv = 1.f / sum;
            float* arow = att + ((size_t)b*Mm + m0 + r)*Mm;
            for (int n = lane; n < Mm; n += 32) {
                float v = Sr[n] * inv;
                Sr[n] = v;
                arow[n] = v;
            }
        }
    }
    __syncthreads();

    // ---------------- phase 2: AV = S @ V ----------------
    float acc2[4][2] = {};
    #pragma unroll 1
    for (int n0 = 0; n0 < Mm; n0 += 128) {
        __syncthreads();
        for (int i = tid; i < 128*32; i += 256) {
            int n = i >> 5, c4 = i & 31;
            reinterpret_cast<float4*>(Ts + n*DOUT)[c4] =
                reinterpret_cast<const float4*>(
                    g_V + ((size_t)b*Mm + n0 + n)*DOUT)[c4];
        }
        __syncthreads();
        #pragma unroll 4
        for (int n = 0; n < 128; n++) {
            float2 v2 = reinterpret_cast<float2*>(Ts + n*DOUT)[cg];
            #pragma unroll
            for (int i = 0; i < 4; i++) {
                float s = S[(rg*4+i)*Mm + n0 + n];    // warp broadcast
                acc2[i][0] = fmaf(s, v2.x, acc2[i][0]);
                acc2[i][1] = fmaf(s, v2.y, acc2[i][1]);
            }
        }
    }
    __syncthreads();
    // park AV in Qs (Q no longer needed)
    #pragma unroll
    for (int i = 0; i < 4; i++) {
        Qs[(rg*4+i)*DOUT + c0    ] = acc2[i][0];
        Qs[(rg*4+i)*DOUT + c0 + 1] = acc2[i][1];
    }
    __syncthreads();

    // ---------------- epilogue: out = l2norm(V + l2norm(AV)) ----------------
    {
        const int w = tid >> 5, lane = tid & 31;
        #pragma unroll 1
        for (int rr = 0; rr < 2; rr++) {
            int r = w*2 + rr;
            float av[4], t[4];
            float ss = 0.f;
            #pragma unroll
            for (int j = 0; j < 4; j++) {
                av[j] = Qs[r*DOUT + lane + j*32];
                ss += av[j]*av[j];
            }
            #pragma unroll
            for (int o = 16; o > 0; o >>= 1)
                ss += __shfl_xor_sync(0xffffffffu, ss, o);
            float inv1 = rsqrtf(fmaxf(ss, 1e-12f));
            const float* vrow = g_V + ((size_t)b*Mm + m0 + r)*DOUT;
            float ss2 = 0.f;
            #pragma unroll
            for (int j = 0; j < 4; j++) {
                t[j] = vrow[lane + j*32] + av[j]*inv1;
                ss2 += t[j]*t[j];
            }
            #pragma unroll
            for (int o = 16; o > 0; o >>= 1)
                ss2 += __shfl_xor_sync(0xffffffffu, ss2, o);
            float inv2 = rsqrtf(fmaxf(ss2, 1e-12f));
            float* orow = out + ((size_t)b*Mm + m0 + r)*DOUT;
            #pragma unroll
            for (int j = 0; j < 4; j++)
                orow[lane + j*32] = t[j]*inv2;
        }
    }
}

// ---------------------------------------------------------------------------
extern "C" void kernel_launch(void* const* d_in, const int* in_sizes, int n_in,
                              void* d_out, int out_size)
{
    const float* Y   = (const float*)d_in[0];
    const int*   idx = (const int*)  d_in[1];
    const float* Wq  = (const float*)d_in[2];
    const float* bq  = (const float*)d_in[3];
    const float* Wk  = (const float*)d_in[4];
    const float* bk  = (const float*)d_in[5];
    const float* Wv  = (const float*)d_in[6];
    const float* bv  = (const float*)d_in[7];

    float* out = (float*)d_out;                       // [8,2048,128]
    float* att = out + (size_t)Bb*Mm*DOUT;            // [8,2048,2048]

    const int smem1 = (32*256 + 64*128) * 4;          // 65536
    const int smem2 = (16*2048 + 16*128 + 128*128)*4; // 204800

    cudaFuncSetAttribute(proj_kernel, cudaFuncAttributeMaxDynamicSharedMemorySize, smem1);
    cudaFuncSetAttribute(attn_kernel, cudaFuncAttributeMaxDynamicSharedMemorySize, smem2);

    proj_kernel<<<(Bb*Mm)/32, 128, smem1>>>(Y, idx, Wq, bq, Wk, bk, Wv, bv);
    attn_kernel<<<dim3(Mm/16, Bb), 256, smem2>>>(out, att);
}

// round 4
// speedup vs baseline: 2.3508x; 2.3508x over previous
#include <cuda_runtime.h>
#include <cuda_bf16.h>
#include <cstdint>

#define Bb   8
#define Nn   4096
#define Mm   2048
#define DIN  256
#define DOUT 128

__device__ __nv_bfloat16 g_Qh [Bb*Mm*DOUT];
__device__ __nv_bfloat16 g_Ql [Bb*Mm*DOUT];
__device__ __nv_bfloat16 g_Kh [Bb*Mm*DOUT];
__device__ __nv_bfloat16 g_Kl [Bb*Mm*DOUT];
__device__ float         g_V  [Bb*Mm*DOUT];
__device__ __nv_bfloat16 g_Vth[Bb*DOUT*Mm];   // [b][e][m]
__device__ __nv_bfloat16 g_Vtl[Bb*DOUT*Mm];

// ---------------- helpers ----------------
__device__ __forceinline__ uint32_t cvta_smem(const void* p) {
    uint32_t a;
    asm("{ .reg .u64 t; cvta.to.shared.u64 t, %1; cvt.u32.u64 %0, t; }" : "=r"(a) : "l"(p));
    return a;
}
__device__ __forceinline__ uint32_t b2pack(float a, float b) {
    uint16_t la = __bfloat16_as_ushort(__float2bfloat16(a));
    uint16_t lb = __bfloat16_as_ushort(__float2bfloat16(b));
    return (uint32_t)la | ((uint32_t)lb << 16);
}
__device__ __forceinline__ float bhi(float x) {
    return __bfloat162float(__float2bfloat16(x));
}

__device__ __forceinline__ void ldmA(uint32_t a[4], uint32_t addr) {
    asm volatile("ldmatrix.sync.aligned.m8n8.x4.shared.b16 {%0,%1,%2,%3}, [%4];"
        : "=r"(a[0]),"=r"(a[1]),"=r"(a[2]),"=r"(a[3]) : "r"(addr));
}
__device__ __forceinline__ void ldmB(uint32_t b[2], uint32_t addr) {
    asm volatile("ldmatrix.sync.aligned.m8n8.x2.shared.b16 {%0,%1}, [%2];"
        : "=r"(b[0]),"=r"(b[1]) : "r"(addr));
}
__device__ __forceinline__ void mma16816(float c[4], const uint32_t a[4], const uint32_t b[2]) {
    asm volatile("mma.sync.aligned.m16n8k16.row.col.f32.bf16.bf16.f32 "
        "{%0,%1,%2,%3}, {%4,%5,%6,%7}, {%8,%9}, {%0,%1,%2,%3};"
        : "+f"(c[0]),"+f"(c[1]),"+f"(c[2]),"+f"(c[3])
        : "r"(a[0]),"r"(a[1]),"r"(a[2]),"r"(a[3]), "r"(b[0]),"r"(b[1]));
}

// pitch: 136 bf16 per smem row (272B) -> conflict-free ldmatrix
#define PIT 136
#define PITB 272

// ---------------------------------------------------------------------------
// Kernel 1: gather + Q/K/V projections; emits bf16 hi/lo splits (Q pre/16).
// ---------------------------------------------------------------------------
__global__ __launch_bounds__(128)
void proj_kernel(const float* __restrict__ Y, const int* __restrict__ idx,
                 const float* __restrict__ Wq, const float* __restrict__ bq,
                 const float* __restrict__ Wk, const float* __restrict__ bk,
                 const float* __restrict__ Wv, const float* __restrict__ bv)
{
    extern __shared__ float sm[];
    float* gS = sm;             // 32*256
    float* Ws = sm + 32*256;    // 64*128 (reused for V transpose staging)
    __shared__ int idxs[32];

    const int tid  = threadIdx.x;
    const int row0 = blockIdx.x * 32;
    const int b    = row0 / Mm;
    const int m0   = row0 % Mm;

    if (tid < 32) idxs[tid] = idx[b*Mm + m0 + tid];
    __syncthreads();

    for (int i = tid; i < 32*64; i += 128) {
        int r = i >> 6, c4 = i & 63;
        const float4* yp = reinterpret_cast<const float4*>(
            Y + ((size_t)b*Nn + idxs[r]) * DIN);
        reinterpret_cast<float4*>(gS + r*DIN)[c4] = yp[c4];
    }

    const int tx = tid & 31;
    const int ty = tid >> 5;
    const int c0 = tx * 4;

    const float* Wlist[3] = {Wq, Wk, Wv};
    const float* blist[3] = {bq, bk, bv};

    #pragma unroll 1
    for (int wsel = 0; wsel < 3; ++wsel) {
        const float* W = Wlist[wsel];
        float acc[8][4];
        {
            float b0v = blist[wsel][c0+0], b1v = blist[wsel][c0+1];
            float b2v = blist[wsel][c0+2], b3v = blist[wsel][c0+3];
            #pragma unroll
            for (int r = 0; r < 8; r++) {
                acc[r][0]=b0v; acc[r][1]=b1v; acc[r][2]=b2v; acc[r][3]=b3v;
            }
        }

        #pragma unroll 1
        for (int k0 = 0; k0 < DIN; k0 += 64) {
            __syncthreads();
            for (int i = tid; i < 64*32; i += 128) {
                int kk = i >> 5, c4 = i & 31;
                reinterpret_cast<float4*>(Ws + kk*DOUT)[c4] =
                    reinterpret_cast<const float4*>(W + (size_t)(k0+kk)*DOUT)[c4];
            }
            __syncthreads();
            #pragma unroll 4
            for (int kk = 0; kk < 64; kk++) {
                float4 w4 = reinterpret_cast<float4*>(Ws + kk*DOUT)[tx];
                #pragma unroll
                for (int r = 0; r < 8; r++) {
                    float gv = gS[(ty*8+r)*DIN + k0 + kk];
                    acc[r][0] = fmaf(gv, w4.x, acc[r][0]);
                    acc[r][1] = fmaf(gv, w4.y, acc[r][1]);
                    acc[r][2] = fmaf(gv, w4.z, acc[r][2]);
                    acc[r][3] = fmaf(gv, w4.w, acc[r][3]);
                }
            }
        }

        if (wsel == 0) {
            #pragma unroll
            for (int r = 0; r < 8; r++) {
                int m = m0 + ty*8 + r;
                float q0=acc[r][0]*0.0625f, q1=acc[r][1]*0.0625f;
                float q2=acc[r][2]*0.0625f, q3=acc[r][3]*0.0625f;
                uint2 h = make_uint2(b2pack(q0,q1), b2pack(q2,q3));
                uint2 l = make_uint2(b2pack(q0-bhi(q0), q1-bhi(q1)),
                                     b2pack(q2-bhi(q2), q3-bhi(q3)));
                size_t o = ((size_t)b*Mm + m)*DOUT + c0;
                *reinterpret_cast<uint2*>(g_Qh + o) = h;
                *reinterpret_cast<uint2*>(g_Ql + o) = l;
            }
        } else if (wsel == 1) {
            #pragma unroll
            for (int r = 0; r < 8; r++) {
                int m = m0 + ty*8 + r;
                float q0=acc[r][0], q1=acc[r][1], q2=acc[r][2], q3=acc[r][3];
                uint2 h = make_uint2(b2pack(q0,q1), b2pack(q2,q3));
                uint2 l = make_uint2(b2pack(q0-bhi(q0), q1-bhi(q1)),
                                     b2pack(q2-bhi(q2), q3-bhi(q3)));
                size_t o = ((size_t)b*Mm + m)*DOUT + c0;
                *reinterpret_cast<uint2*>(g_Kh + o) = h;
                *reinterpret_cast<uint2*>(g_Kl + o) = l;
            }
        } else {
            #pragma unroll
            for (int r = 0; r < 8; r++) {
                int m = m0 + ty*8 + r;
                #pragma unroll
                for (int j = 0; j < 4; j++) acc[r][j] = fmaxf(acc[r][j], 0.f);
                float4 v4 = make_float4(acc[r][0],acc[r][1],acc[r][2],acc[r][3]);
                reinterpret_cast<float4*>(g_V + ((size_t)b*Mm + m)*DOUT)[tx] = v4;
            }
            __syncthreads();
            float* sv = Ws;   // staging [32][pitch 132]
            #pragma unroll
            for (int r = 0; r < 8; r++)
                #pragma unroll
                for (int j = 0; j < 4; j++)
                    sv[(ty*8+r)*132 + c0 + j] = acc[r][j];
            __syncthreads();
            uint32_t hp[16], lp[16];
            #pragma unroll
            for (int m2 = 0; m2 < 16; m2++) {
                float x0 = sv[(2*m2  )*132 + tid];
                float x1 = sv[(2*m2+1)*132 + tid];
                hp[m2] = b2pack(x0, x1);
                lp[m2] = b2pack(x0 - bhi(x0), x1 - bhi(x1));
            }
            uint4* dh = reinterpret_cast<uint4*>(g_Vth + ((size_t)b*DOUT + tid)*Mm + m0);
            uint4* dl = reinterpret_cast<uint4*>(g_Vtl + ((size_t)b*DOUT + tid)*Mm + m0);
            #pragma unroll
            for (int q = 0; q < 4; q++) {
                dh[q] = make_uint4(hp[4*q],hp[4*q+1],hp[4*q+2],hp[4*q+3]);
                dl[q] = make_uint4(lp[4*q],lp[4*q+1],lp[4*q+2],lp[4*q+3]);
            }
        }
    }
}

// ---------------------------------------------------------------------------
// Kernel A: S = (Q/16) K^T (split-bf16 mma.sync), stream to att, softmax.
// 256 threads = 8 warps in 4(m) x 2(n); warp tile 32 x 64.
// ---------------------------------------------------------------------------
__global__ __launch_bounds__(256, 1)
void attnA_kernel(float* __restrict__ att)
{
    extern __shared__ char smraw[];
    const int tid = threadIdx.x, lane = tid & 31, wid = tid >> 5;
    const int b = blockIdx.y, m0 = blockIdx.x * 128;
    const int wm = wid >> 1, wn = wid & 1;

    char* Qh = smraw;
    char* Ql = smraw + 34816;
    char* Kh = smraw + 69632;
    char* Kl = smraw + 104448;
    float* Ss = reinterpret_cast<float*>(smraw + 69632);   // aliases K (phase-separated)

    // load Q hi/lo into padded smem
    {
        const uint4* qh = reinterpret_cast<const uint4*>(g_Qh + ((size_t)b*Mm + m0)*DOUT);
        const uint4* ql = reinterpret_cast<const uint4*>(g_Ql + ((size_t)b*Mm + m0)*DOUT);
        for (int i = tid; i < 128*16; i += 256) {
            int row = i >> 4, c8 = i & 15;
            *reinterpret_cast<uint4*>(Qh + row*PITB + c8*16) = qh[i];
            *reinterpret_cast<uint4*>(Ql + row*PITB + c8*16) = ql[i];
        }
    }

    const uint32_t sQh = cvta_smem(Qh), sQl = cvta_smem(Ql);
    const uint32_t sKh = cvta_smem(Kh), sKl = cvta_smem(Kl);

    const int aRow = wm*32 + (lane & 15);       // + mi*16
    const int aKb  = (lane >> 4) * 8;           // + ks*16
    const int bRow = wn*64 + (lane & 7);        // + j*8
    const int bKb  = ((lane >> 3) & 1) * 8;     // + ks*16

    #pragma unroll 1
    for (int ch = 0; ch < 16; ch++) {
        const uint4* kh = reinterpret_cast<const uint4*>(g_Kh + ((size_t)b*Mm + ch*128)*DOUT);
        const uint4* kl = reinterpret_cast<const uint4*>(g_Kl + ((size_t)b*Mm + ch*128)*DOUT);
        for (int i = tid; i < 128*16; i += 256) {
            int row = i >> 4, c8 = i & 15;
            *reinterpret_cast<uint4*>(Kh + row*PITB + c8*16) = kh[i];
            *reinterpret_cast<uint4*>(Kl + row*PITB + c8*16) = kl[i];
        }
        __syncthreads();

        float acc[2][8][4] = {};
        #pragma unroll
        for (int term = 0; term < 3; term++) {
            uint32_t sA = (term == 2) ? sQl : sQh;
            uint32_t sB = (term == 1) ? sKl : sKh;
            #pragma unroll
            for (int ks = 0; ks < 8; ks++) {
                uint32_t af[2][4], bf[8][2];
                #pragma unroll
                for (int mi = 0; mi < 2; mi++)
                    ldmA(af[mi], sA + ((aRow + mi*16)*PIT + aKb + ks*16)*2);
                #pragma unroll
                for (int j = 0; j < 8; j++)
                    ldmB(bf[j], sB + ((bRow + j*8)*PIT + bKb + ks*16)*2);
                #pragma unroll
                for (int mi = 0; mi < 2; mi++)
                    #pragma unroll
                    for (int j = 0; j < 8; j++)
                        mma16816(acc[mi][j], af[mi], bf[j]);
            }
        }
        __syncthreads();   // all warps done reading K before Ss overwrite

        #pragma unroll
        for (int mi = 0; mi < 2; mi++)
            #pragma unroll
            for (int j = 0; j < 8; j++) {
                int r = wm*32 + mi*16 + (lane >> 2);
                int c = wn*64 + j*8 + (lane & 3)*2;
                Ss[r*132 + c]         = acc[mi][j][0];
                Ss[r*132 + c + 1]     = acc[mi][j][1];
                Ss[(r+8)*132 + c]     = acc[mi][j][2];
                Ss[(r+8)*132 + c + 1] = acc[mi][j][3];
            }
        __syncthreads();

        for (int i = tid; i < 128*32; i += 256) {
            int row = i >> 5, c4 = i & 31;
            float4 v = *reinterpret_cast<float4*>(Ss + row*132 + c4*4);
            *reinterpret_cast<float4*>(
                att + ((size_t)(b*Mm + m0 + row))*Mm + ch*128 + c4*4) = v;
        }
        __syncthreads();
    }

    // softmax: warp wid owns rows [wid*16, wid*16+16)
    #pragma unroll 1
    for (int rr = 0; rr < 16; rr++) {
        float* row = att + ((size_t)(b*Mm + m0 + wid*16 + rr))*Mm;
        float4 v[16];
        #pragma unroll
        for (int j = 0; j < 16; j++) v[j] = reinterpret_cast<float4*>(row)[lane + j*32];
        float mx = -1e30f;
        #pragma unroll
        for (int j = 0; j < 16; j++)
            mx = fmaxf(mx, fmaxf(fmaxf(v[j].x, v[j].y), fmaxf(v[j].z, v[j].w)));
        #pragma unroll
        for (int o = 16; o > 0; o >>= 1) mx = fmaxf(mx, __shfl_xor_sync(0xffffffffu, mx, o));
        float sum = 0.f;
        #pragma unroll
        for (int j = 0; j < 16; j++) {
            v[j].x = __expf(v[j].x - mx); v[j].y = __expf(v[j].y - mx);
            v[j].z = __expf(v[j].z - mx); v[j].w = __expf(v[j].w - mx);
            sum += (v[j].x + v[j].y) + (v[j].z + v[j].w);
        }
        #pragma unroll
        for (int o = 16; o > 0; o >>= 1) sum += __shfl_xor_sync(0xffffffffu, sum, o);
        float inv = 1.f / sum;
        #pragma unroll
        for (int j = 0; j < 16; j++) {
            v[j].x *= inv; v[j].y *= inv; v[j].z *= inv; v[j].w *= inv;
            reinterpret_cast<float4*>(row)[lane + j*32] = v[j];
        }
    }
}

// ---------------------------------------------------------------------------
// Kernel C: AV = att @ V (att split on the fly, B = V^T hi/lo), l2norm epilogue.
// ---------------------------------------------------------------------------
__global__ __launch_bounds__(256, 1)
void attnC_kernel(const float* __restrict__ att, float* __restrict__ out)
{
    extern __shared__ char smraw[];
    const int tid = threadIdx.x, lane = tid & 31, wid = tid >> 5;
    const int b = blockIdx.y, m0 = blockIdx.x * 128;
    const int wm = wid >> 1, wn = wid & 1;

    char* Ah = smraw;
    char* Al = smraw + 34816;
    char* Bh = smraw + 69632;
    char* Bl = smraw + 104448;
    float* Ss = reinterpret_cast<float*>(smraw);           // aliases A (phase-separated)

    const uint32_t sAh = cvta_smem(Ah), sAl = cvta_smem(Al);
    const uint32_t sBh = cvta_smem(Bh), sBl = cvta_smem(Bl);

    const int aRow = wm*32 + (lane & 15);
    const int aKb  = (lane >> 4) * 8;
    const int bRow = wn*64 + (lane & 7);
    const int bKb  = ((lane >> 3) & 1) * 8;

    float acc[2][8][4] = {};

    #pragma unroll 1
    for (int ch = 0; ch < 16; ch++) {
        // att chunk fp32 -> hi/lo bf16
        const float* ab = att + ((size_t)(b*Mm + m0))*Mm + ch*128;
        for (int i = tid; i < 128*32; i += 256) {
            int row = i >> 5, c4 = i & 31;
            float4 v = *reinterpret_cast<const float4*>(ab + (size_t)row*Mm + c4*4);
            uint2 h = make_uint2(b2pack(v.x, v.y), b2pack(v.z, v.w));
            uint2 l = make_uint2(b2pack(v.x-bhi(v.x), v.y-bhi(v.y)),
                                 b2pack(v.z-bhi(v.z), v.w-bhi(v.w)));
            *reinterpret_cast<uint2*>(Ah + row*PITB + c4*8) = h;
            *reinterpret_cast<uint2*>(Al + row*PITB + c4*8) = l;
        }
        // V^T chunk (rows = e, cols = keys)
        for (int i = tid; i < 128*16; i += 256) {
            int row = i >> 4, c8 = i & 15;
            size_t go = ((size_t)b*DOUT + row)*Mm + ch*128 + c8*8;
            *reinterpret_cast<uint4*>(Bh + row*PITB + c8*16) =
                *reinterpret_cast<const uint4*>(g_Vth + go);
            *reinterpret_cast<uint4*>(Bl + row*PITB + c8*16) =
                *reinterpret_cast<const uint4*>(g_Vtl + go);
        }
        __syncthreads();

        #pragma unroll
        for (int term = 0; term < 3; term++) {
            uint32_t sA = (term == 2) ? sAl : sAh;
            uint32_t sB = (term == 1) ? sBl : sBh;
            #pragma unroll
            for (int ks = 0; ks < 8; ks++) {
                uint32_t af[2][4], bf[8][2];
                #pragma unroll
                for (int mi = 0; mi < 2; mi++)
                    ldmA(af[mi], sA + ((aRow + mi*16)*PIT + aKb + ks*16)*2);
                #pragma unroll
                for (int j = 0; j < 8; j++)
                    ldmB(bf[j], sB + ((bRow + j*8)*PIT + bKb + ks*16)*2);
                #pragma unroll
                for (int mi = 0; mi < 2; mi++)
                    #pragma unroll
                    for (int j = 0; j < 8; j++)
                        mma16816(acc[mi][j], af[mi], bf[j]);
            }
        }
        __syncthreads();
    }

    // acc -> Ss (AV tile 128x128, pitch 132)
    #pragma unroll
    for (int mi = 0; mi < 2; mi++)
        #pragma unroll
        for (int j = 0; j < 8; j++) {
            int r = wm*32 + mi*16 + (lane >> 2);
            int c = wn*64 + j*8 + (lane & 3)*2;
            Ss[r*132 + c]         = acc[mi][j][0];
            Ss[r*132 + c + 1]     = acc[mi][j][1];
            Ss[(r+8)*132 + c]     = acc[mi][j][2];
            Ss[(r+8)*132 + c + 1] = acc[mi][j][3];
        }
    __syncthreads();

    // epilogue: out = l2norm(V + l2norm(AV)); warp wid owns rows wid*16..+15
    #pragma unroll 1
    for (int rr = 0; rr < 16; rr++) {
        int r = wid*16 + rr;
        float a0 = Ss[r*132 + lane],      a1 = Ss[r*132 + lane + 32];
        float a2 = Ss[r*132 + lane + 64], a3 = Ss[r*132 + lane + 96];
        float ss = a0*a0 + a1*a1 + a2*a2 + a3*a3;
        #pragma unroll
        for (int o = 16; o > 0; o >>= 1) ss += __shfl_xor_sync(0xffffffffu, ss, o);
        float inv1 = rsqrtf(fmaxf(ss, 1e-12f));
        const float* vrow = g_V + ((size_t)b*Mm + m0 + r)*DOUT;
        float t0 = vrow[lane]      + a0*inv1;
        float t1 = vrow[lane + 32] + a1*inv1;
        float t2 = vrow[lane + 64] + a2*inv1;
        float t3 = vrow[lane + 96] + a3*inv1;
        float ss2 = t0*t0 + t1*t1 + t2*t2 + t3*t3;
        #pragma unroll
        for (int o = 16; o > 0; o >>= 1) ss2 += __shfl_xor_sync(0xffffffffu, ss2, o);
        float inv2 = rsqrtf(fmaxf(ss2, 1e-12f));
        float* orow = out + ((size_t)b*Mm + m0 + r)*DOUT;
        orow[lane]      = t0*inv2;
        orow[lane + 32] = t1*inv2;
        orow[lane + 64] = t2*inv2;
        orow[lane + 96] = t3*inv2;
    }
}

// ---------------------------------------------------------------------------
extern "C" void kernel_launch(void* const* d_in, const int* in_sizes, int n_in,
                              void* d_out, int out_size)
{
    const float* Y   = (const float*)d_in[0];
    const int*   idx = (const int*)  d_in[1];
    const float* Wq  = (const float*)d_in[2];
    const float* bq  = (const float*)d_in[3];
    const float* Wk  = (const float*)d_in[4];
    const float* bk  = (const float*)d_in[5];
    const float* Wv  = (const float*)d_in[6];
    const float* bv  = (const float*)d_in[7];

    float* out = (float*)d_out;                       // [8,2048,128]
    float* att = out + (size_t)Bb*Mm*DOUT;            // [8,2048,2048]

    const int smem1 = (32*256 + 64*128) * 4;          // 64 KB
    const int smemG = 4 * 128 * PITB;                 // 139264 B

    cudaFuncSetAttribute(proj_kernel,  cudaFuncAttributeMaxDynamicSharedMemorySize, smem1);
    cudaFuncSetAttribute(attnA_kernel, cudaFuncAttributeMaxDynamicSharedMemorySize, smemG);
    cudaFuncSetAttribute(attnC_kernel, cudaFuncAttributeMaxDynamicSharedMemorySize, smemG);

    proj_kernel<<<(Bb*Mm)/32, 128, smem1>>>(Y, idx, Wq, bq, Wk, bk, Wv, bv);
    attnA_kernel<<<dim3(Mm/128, Bb), 256, smemG>>>(att);
    attnC_kernel<<<dim3(Mm/128, Bb), 256, smemG>>>(att, out);
}

// round 5
// speedup vs baseline: 3.1170x; 1.3259x over previous
#include <cuda_runtime.h>
#include <cuda_bf16.h>
#include <cstdint>

#define Bb   8
#define Nn   4096
#define Mm   2048
#define DIN  256
#define DOUT 128

__device__ __nv_bfloat16 g_Qh [Bb*Mm*DOUT];
__device__ __nv_bfloat16 g_Ql [Bb*Mm*DOUT];
__device__ __nv_bfloat16 g_Kh [Bb*Mm*DOUT];
__device__ __nv_bfloat16 g_Kl [Bb*Mm*DOUT];
__device__ float         g_V  [Bb*Mm*DOUT];
__device__ __nv_bfloat16 g_Vth[Bb*DOUT*Mm];    // [b][e][m]
__device__ __nv_bfloat16 g_Vtl[Bb*DOUT*Mm];
__device__ __nv_bfloat16 g_Wth[3*DOUT*DIN];    // [wsel][n][k]
__device__ __nv_bfloat16 g_Wtl[3*DOUT*DIN];

// ---------------- helpers ----------------
__device__ __forceinline__ uint32_t cvta_smem(const void* p) {
    uint32_t a;
    asm("{ .reg .u64 t; cvta.to.shared.u64 t, %1; cvt.u32.u64 %0, t; }" : "=r"(a) : "l"(p));
    return a;
}
__device__ __forceinline__ uint32_t b2pack(float a, float b) {
    uint16_t la = __bfloat16_as_ushort(__float2bfloat16(a));
    uint16_t lb = __bfloat16_as_ushort(__float2bfloat16(b));
    return (uint32_t)la | ((uint32_t)lb << 16);
}
__device__ __forceinline__ float bhi(float x) {
    return __bfloat162float(__float2bfloat16(x));
}
__device__ __forceinline__ void ldmA(uint32_t a[4], uint32_t addr) {
    asm volatile("ldmatrix.sync.aligned.m8n8.x4.shared.b16 {%0,%1,%2,%3}, [%4];"
        : "=r"(a[0]),"=r"(a[1]),"=r"(a[2]),"=r"(a[3]) : "r"(addr));
}
__device__ __forceinline__ void ldmB(uint32_t b[2], uint32_t addr) {
    asm volatile("ldmatrix.sync.aligned.m8n8.x2.shared.b16 {%0,%1}, [%2];"
        : "=r"(b[0]),"=r"(b[1]) : "r"(addr));
}
__device__ __forceinline__ void mma16816(float c[4], const uint32_t a[4], const uint32_t b[2]) {
    asm volatile("mma.sync.aligned.m16n8k16.row.col.f32.bf16.bf16.f32 "
        "{%0,%1,%2,%3}, {%4,%5,%6,%7}, {%8,%9}, {%0,%1,%2,%3};"
        : "+f"(c[0]),"+f"(c[1]),"+f"(c[2]),"+f"(c[3])
        : "r"(a[0]),"r"(a[1]),"r"(a[2]),"r"(a[3]), "r"(b[0]),"r"(b[1]));
}

#define PIT 136
#define PITB 272

// ---------------------------------------------------------------------------
// prep: W[k][n] fp32 -> W^T[n][k] bf16 hi/lo (3 matrices). grid=3, block=256.
// ---------------------------------------------------------------------------
__global__ void prep_kernel(const float* __restrict__ Wq,
                            const float* __restrict__ Wk,
                            const float* __restrict__ Wv)
{
    const float* W = (blockIdx.x == 0) ? Wq : (blockIdx.x == 1) ? Wk : Wv;
    __nv_bfloat16* dh = g_Wth + blockIdx.x * DOUT * DIN;
    __nv_bfloat16* dl = g_Wtl + blockIdx.x * DOUT * DIN;
    for (int i = threadIdx.x; i < DOUT * (DIN/2); i += 256) {
        int n = i >> 7, k = (i & 127) * 2;
        float x0 = W[(size_t)k*DOUT + n];
        float x1 = W[(size_t)(k+1)*DOUT + n];
        *reinterpret_cast<uint32_t*>(dh + (size_t)n*DIN + k) = b2pack(x0, x1);
        *reinterpret_cast<uint32_t*>(dl + (size_t)n*DIN + k) =
            b2pack(x0 - bhi(x0), x1 - bhi(x1));
    }
}

// ---------------------------------------------------------------------------
// projmma: gather + Q/K/V projections via split-bf16 mma.sync.
// CTA = 128 gathered rows; 256 threads, 8 warps (4m x 2n), warp tile 32x64.
// smem: Ah[2 chunks] 69632 | Al 69632 | Bh 34816 | Bl 34816 = 208896 B.
// ---------------------------------------------------------------------------
__global__ __launch_bounds__(256, 1)
void projmma_kernel(const float* __restrict__ Y, const int* __restrict__ idx,
                    const float* __restrict__ bq, const float* __restrict__ bk,
                    const float* __restrict__ bv)
{
    extern __shared__ char smraw[];
    char* Ah = smraw;                    // 2 chunks x 34816
    char* Al = smraw + 69632;
    char* Bh = smraw + 139264;
    char* Bl = smraw + 174080;
    float* Vs = reinterpret_cast<float*>(Bh);   // 128x132 fp32, phase-separated
    __shared__ int idxs[128];

    const int tid = threadIdx.x, lane = tid & 31, wid = tid >> 5;
    const int wm = wid >> 1, wn = wid & 1;
    const int row0 = blockIdx.x * 128;
    const int b    = row0 / Mm;
    const int m0   = row0 % Mm;

    if (tid < 128) idxs[tid] = idx[b*Mm + m0 + tid];
    __syncthreads();

    // gather + split A: Y rows fp32 -> bf16 hi/lo, two 128-k chunks
    for (int i = tid; i < 128*64; i += 256) {
        int row = i >> 6, c4 = i & 63;                 // c4: float4 index in 256
        float4 y = *reinterpret_cast<const float4*>(
            Y + ((size_t)b*Nn + idxs[row])*DIN + c4*4);
        int kc = c4 >> 5;
        uint32_t off = (uint32_t)(kc*34816 + row*PITB + (c4 & 31)*8);
        *reinterpret_cast<uint2*>(Ah + off) =
            make_uint2(b2pack(y.x, y.y), b2pack(y.z, y.w));
        *reinterpret_cast<uint2*>(Al + off) =
            make_uint2(b2pack(y.x-bhi(y.x), y.y-bhi(y.y)),
                       b2pack(y.z-bhi(y.z), y.w-bhi(y.w)));
    }

    const uint32_t sAh = cvta_smem(Ah), sAl = cvta_smem(Al);
    const uint32_t sBh = cvta_smem(Bh), sBl = cvta_smem(Bl);

    const int aRow = wm*32 + (lane & 15);
    const int aKb  = (lane >> 4) * 8;
    const int bRow = wn*64 + (lane & 7);
    const int bKb  = ((lane >> 3) & 1) * 8;

    #pragma unroll 1
    for (int wsel = 0; wsel < 3; wsel++) {
        float acc[2][8][4] = {};
        #pragma unroll 1
        for (int kc = 0; kc < 2; kc++) {
            __syncthreads();   // previous B consumed (and gather done on first pass)
            const __nv_bfloat16* wh = g_Wth + (size_t)wsel*DOUT*DIN + kc*128;
            const __nv_bfloat16* wl = g_Wtl + (size_t)wsel*DOUT*DIN + kc*128;
            for (int i = tid; i < 128*16; i += 256) {
                int n = i >> 4, c8 = i & 15;
                uint32_t off = (uint32_t)(n*PITB + c8*16);
                size_t go = (size_t)n*DIN + c8*8;
                *reinterpret_cast<uint4*>(Bh + off) =
                    *reinterpret_cast<const uint4*>(wh + go);
                *reinterpret_cast<uint4*>(Bl + off) =
                    *reinterpret_cast<const uint4*>(wl + go);
            }
            __syncthreads();
            uint32_t aBase = kc * 34816;
            #pragma unroll
            for (int term = 0; term < 3; term++) {
                uint32_t sA = ((term == 2) ? sAl : sAh) + aBase;
                uint32_t sB = (term == 1) ? sBl : sBh;
                #pragma unroll
                for (int ks = 0; ks < 8; ks++) {
                    uint32_t af[2][4], bf[8][2];
                    #pragma unroll
                    for (int mi = 0; mi < 2; mi++)
                        ldmA(af[mi], sA + ((aRow + mi*16)*PIT + aKb + ks*16)*2);
                    #pragma unroll
                    for (int j = 0; j < 8; j++)
                        ldmB(bf[j], sB + ((bRow + j*8)*PIT + bKb + ks*16)*2);
                    #pragma unroll
                    for (int mi = 0; mi < 2; mi++)
                        #pragma unroll
                        for (int j = 0; j < 8; j++)
                            mma16816(acc[mi][j], af[mi], bf[j]);
                }
            }
        }

        // bias for this thread's 8 column pairs
        const float* bp = (wsel == 0) ? bq : (wsel == 1) ? bk : bv;
        float bias2[8][2];
        #pragma unroll
        for (int j = 0; j < 8; j++) {
            int c = wn*64 + j*8 + (lane & 3)*2;
            bias2[j][0] = bp[c]; bias2[j][1] = bp[c+1];
        }

        if (wsel < 2) {
            const float s = (wsel == 0) ? 0.0625f : 1.0f;
            __nv_bfloat16* gh = (wsel == 0) ? g_Qh : g_Kh;
            __nv_bfloat16* gl = (wsel == 0) ? g_Ql : g_Kl;
            #pragma unroll
            for (int mi = 0; mi < 2; mi++)
                #pragma unroll
                for (int j = 0; j < 8; j++) {
                    int r = wm*32 + mi*16 + (lane >> 2);
                    int c = wn*64 + j*8 + (lane & 3)*2;
                    float q0 = (acc[mi][j][0] + bias2[j][0]) * s;
                    float q1 = (acc[mi][j][1] + bias2[j][1]) * s;
                    float q2 = (acc[mi][j][2] + bias2[j][0]) * s;
                    float q3 = (acc[mi][j][3] + bias2[j][1]) * s;
                    size_t o0 = ((size_t)(b*Mm + m0 + r))*DOUT + c;
                    size_t o1 = ((size_t)(b*Mm + m0 + r + 8))*DOUT + c;
                    *reinterpret_cast<uint32_t*>(gh + o0) = b2pack(q0, q1);
                    *reinterpret_cast<uint32_t*>(gl + o0) =
                        b2pack(q0 - bhi(q0), q1 - bhi(q1));
                    *reinterpret_cast<uint32_t*>(gh + o1) = b2pack(q2, q3);
                    *reinterpret_cast<uint32_t*>(gl + o1) =
                        b2pack(q2 - bhi(q2), q3 - bhi(q3));
                }
        } else {
            // V: relu, fp32 store + smem staging for transpose
            __syncthreads();    // all warps done reading B before Vs overwrite
            #pragma unroll
            for (int mi = 0; mi < 2; mi++)
                #pragma unroll
                for (int j = 0; j < 8; j++) {
                    int r = wm*32 + mi*16 + (lane >> 2);
                    int c = wn*64 + j*8 + (lane & 3)*2;
                    float v0 = fmaxf(acc[mi][j][0] + bias2[j][0], 0.f);
                    float v1 = fmaxf(acc[mi][j][1] + bias2[j][1], 0.f);
                    float v2 = fmaxf(acc[mi][j][2] + bias2[j][0], 0.f);
                    float v3 = fmaxf(acc[mi][j][3] + bias2[j][1], 0.f);
                    *reinterpret_cast<float2*>(
                        g_V + ((size_t)(b*Mm + m0 + r))*DOUT + c) = make_float2(v0, v1);
                    *reinterpret_cast<float2*>(
                        g_V + ((size_t)(b*Mm + m0 + r + 8))*DOUT + c) = make_float2(v2, v3);
                    Vs[r*132 + c]       = v0;
                    Vs[r*132 + c + 1]   = v1;
                    Vs[(r+8)*132 + c]   = v2;
                    Vs[(r+8)*132 + c+1] = v3;
                }
            __syncthreads();
            // transposed hi/lo write: thread -> (e = tid&127, half = tid>>7)
            int e = tid & 127, half = tid >> 7;
            #pragma unroll
            for (int seg = 0; seg < 2; seg++) {
                int mb = half*64 + seg*32;
                uint32_t hp[16], lp[16];
                #pragma unroll
                for (int t = 0; t < 16; t++) {
                    float x0 = Vs[(mb + 2*t    )*132 + e];
                    float x1 = Vs[(mb + 2*t + 1)*132 + e];
                    hp[t] = b2pack(x0, x1);
                    lp[t] = b2pack(x0 - bhi(x0), x1 - bhi(x1));
                }
                uint4* dh = reinterpret_cast<uint4*>(
                    g_Vth + ((size_t)b*DOUT + e)*Mm + m0 + mb);
                uint4* dl = reinterpret_cast<uint4*>(
                    g_Vtl + ((size_t)b*DOUT + e)*Mm + m0 + mb);
                #pragma unroll
                for (int q = 0; q < 4; q++) {
                    dh[q] = make_uint4(hp[4*q],hp[4*q+1],hp[4*q+2],hp[4*q+3]);
                    dl[q] = make_uint4(lp[4*q],lp[4*q+1],lp[4*q+2],lp[4*q+3]);
                }
            }
        }
    }
}

// ---------------------------------------------------------------------------
// Kernel A: S = (Q/16) K^T (split-bf16 mma.sync), stream to att, softmax.
// ---------------------------------------------------------------------------
__global__ __launch_bounds__(256, 1)
void attnA_kernel(float* __restrict__ att)
{
    extern __shared__ char smraw[];
    const int tid = threadIdx.x, lane = tid & 31, wid = tid >> 5;
    const int b = blockIdx.y, m0 = blockIdx.x * 128;
    const int wm = wid >> 1, wn = wid & 1;

    char* Qh = smraw;
    char* Ql = smraw + 34816;
    char* Kh = smraw + 69632;
    char* Kl = smraw + 104448;
    float* Ss = reinterpret_cast<float*>(smraw + 69632);

    {
        const uint4* qh = reinterpret_cast<const uint4*>(g_Qh + ((size_t)b*Mm + m0)*DOUT);
        const uint4* ql = reinterpret_cast<const uint4*>(g_Ql + ((size_t)b*Mm + m0)*DOUT);
        for (int i = tid; i < 128*16; i += 256) {
            int row = i >> 4, c8 = i & 15;
            *reinterpret_cast<uint4*>(Qh + row*PITB + c8*16) = qh[i];
            *reinterpret_cast<uint4*>(Ql + row*PITB + c8*16) = ql[i];
        }
    }

    const uint32_t sQh = cvta_smem(Qh), sQl = cvta_smem(Ql);
    const uint32_t sKh = cvta_smem(Kh), sKl = cvta_smem(Kl);

    const int aRow = wm*32 + (lane & 15);
    const int aKb  = (lane >> 4) * 8;
    const int bRow = wn*64 + (lane & 7);
    const int bKb  = ((lane >> 3) & 1) * 8;

    #pragma unroll 1
    for (int ch = 0; ch < 16; ch++) {
        const uint4* kh = reinterpret_cast<const uint4*>(g_Kh + ((size_t)b*Mm + ch*128)*DOUT);
        const uint4* kl = reinterpret_cast<const uint4*>(g_Kl + ((size_t)b*Mm + ch*128)*DOUT);
        for (int i = tid; i < 128*16; i += 256) {
            int row = i >> 4, c8 = i & 15;
            *reinterpret_cast<uint4*>(Kh + row*PITB + c8*16) = kh[i];
            *reinterpret_cast<uint4*>(Kl + row*PITB + c8*16) = kl[i];
        }
        __syncthreads();

        float acc[2][8][4] = {};
        #pragma unroll
        for (int term = 0; term < 3; term++) {
            uint32_t sA = (term == 2) ? sQl : sQh;
            uint32_t sB = (term == 1) ? sKl : sKh;
            #pragma unroll
            for (int ks = 0; ks < 8; ks++) {
                uint32_t af[2][4], bf[8][2];
                #pragma unroll
                for (int mi = 0; mi < 2; mi++)
                    ldmA(af[mi], sA + ((aRow + mi*16)*PIT + aKb + ks*16)*2);
                #pragma unroll
                for (int j = 0; j < 8; j++)
                    ldmB(bf[j], sB + ((bRow + j*8)*PIT + bKb + ks*16)*2);
                #pragma unroll
                for (int mi = 0; mi < 2; mi++)
                    #pragma unroll
                    for (int j = 0; j < 8; j++)
                        mma16816(acc[mi][j], af[mi], bf[j]);
            }
        }
        __syncthreads();

        #pragma unroll
        for (int mi = 0; mi < 2; mi++)
            #pragma unroll
            for (int j = 0; j < 8; j++) {
                int r = wm*32 + mi*16 + (lane >> 2);
                int c = wn*64 + j*8 + (lane & 3)*2;
                Ss[r*132 + c]         = acc[mi][j][0];
                Ss[r*132 + c + 1]     = acc[mi][j][1];
                Ss[(r+8)*132 + c]     = acc[mi][j][2];
                Ss[(r+8)*132 + c + 1] = acc[mi][j][3];
            }
        __syncthreads();

        for (int i = tid; i < 128*32; i += 256) {
            int row = i >> 5, c4 = i & 31;
            float4 v = *reinterpret_cast<float4*>(Ss + row*132 + c4*4);
            *reinterpret_cast<float4*>(
                att + ((size_t)(b*Mm + m0 + row))*Mm + ch*128 + c4*4) = v;
        }
        __syncthreads();
    }

    #pragma unroll 1
    for (int rr = 0; rr < 16; rr++) {
        float* row = att + ((size_t)(b*Mm + m0 + wid*16 + rr))*Mm;
        float4 v[16];
        #pragma unroll
        for (int j = 0; j < 16; j++) v[j] = reinterpret_cast<float4*>(row)[lane + j*32];
        float mx = -1e30f;
        #pragma unroll
        for (int j = 0; j < 16; j++)
            mx = fmaxf(mx, fmaxf(fmaxf(v[j].x, v[j].y), fmaxf(v[j].z, v[j].w)));
        #pragma unroll
        for (int o = 16; o > 0; o >>= 1) mx = fmaxf(mx, __shfl_xor_sync(0xffffffffu, mx, o));
        float sum = 0.f;
        #pragma unroll
        for (int j = 0; j < 16; j++) {
            v[j].x = __expf(v[j].x - mx); v[j].y = __expf(v[j].y - mx);
            v[j].z = __expf(v[j].z - mx); v[j].w = __expf(v[j].w - mx);
            sum += (v[j].x + v[j].y) + (v[j].z + v[j].w);
        }
        #pragma unroll
        for (int o = 16; o > 0; o >>= 1) sum += __shfl_xor_sync(0xffffffffu, sum, o);
        float inv = 1.f / sum;
        #pragma unroll
        for (int j = 0; j < 16; j++) {
            v[j].x *= inv; v[j].y *= inv; v[j].z *= inv; v[j].w *= inv;
            reinterpret_cast<float4*>(row)[lane + j*32] = v[j];
        }
    }
}

// ---------------------------------------------------------------------------
// Kernel C: AV = att @ V (att split on the fly, B = V^T hi/lo), l2norm epilogue.
// ---------------------------------------------------------------------------
__global__ __launch_bounds__(256, 1)
void attnC_kernel(const float* __restrict__ att, float* __restrict__ out)
{
    extern __shared__ char smraw[];
    const int tid = threadIdx.x, lane = tid & 31, wid = tid >> 5;
    const int b = blockIdx.y, m0 = blockIdx.x * 128;
    const int wm = wid >> 1, wn = wid & 1;

    char* Ah = smraw;
    char* Al = smraw + 34816;
    char* Bh = smraw + 69632;
    char* Bl = smraw + 104448;
    float* Ss = reinterpret_cast<float*>(smraw);

    const uint32_t sAh = cvta_smem(Ah), sAl = cvta_smem(Al);
    const uint32_t sBh = cvta_smem(Bh), sBl = cvta_smem(Bl);

    const int aRow = wm*32 + (lane & 15);
    const int aKb  = (lane >> 4) * 8;
    const int bRow = wn*64 + (lane & 7);
    const int bKb  = ((lane >> 3) & 1) * 8;

    float acc[2][8][4] = {};

    #pragma unroll 1
    for (int ch = 0; ch < 16; ch++) {
        const float* ab = att + ((size_t)(b*Mm + m0))*Mm + ch*128;
        for (int i = tid; i < 128*32; i += 256) {
            int row = i >> 5, c4 = i & 31;
            float4 v = *reinterpret_cast<const float4*>(ab + (size_t)row*Mm + c4*4);
            uint2 h = make_uint2(b2pack(v.x, v.y), b2pack(v.z, v.w));
            uint2 l = make_uint2(b2pack(v.x-bhi(v.x), v.y-bhi(v.y)),
                                 b2pack(v.z-bhi(v.z), v.w-bhi(v.w)));
            *reinterpret_cast<uint2*>(Ah + row*PITB + c4*8) = h;
            *reinterpret_cast<uint2*>(Al + row*PITB + c4*8) = l;
        }
        for (int i = tid; i < 128*16; i += 256) {
            int row = i >> 4, c8 = i & 15;
            size_t go = ((size_t)b*DOUT + row)*Mm + ch*128 + c8*8;
            *reinterpret_cast<uint4*>(Bh + row*PITB + c8*16) =
                *reinterpret_cast<const uint4*>(g_Vth + go);
            *reinterpret_cast<uint4*>(Bl + row*PITB + c8*16) =
                *reinterpret_cast<const uint4*>(g_Vtl + go);
        }
        __syncthreads();

        #pragma unroll
        for (int term = 0; term < 3; term++) {
            uint32_t sA = (term == 2) ? sAl : sAh;
            uint32_t sB = (term == 1) ? sBl : sBh;
            #pragma unroll
            for (int ks = 0; ks < 8; ks++) {
                uint32_t af[2][4], bf[8][2];
                #pragma unroll
                for (int mi = 0; mi < 2; mi++)
                    ldmA(af[mi], sA + ((aRow + mi*16)*PIT + aKb + ks*16)*2);
                #pragma unroll
                for (int j = 0; j < 8; j++)
                    ldmB(bf[j], sB + ((bRow + j*8)*PIT + bKb + ks*16)*2);
                #pragma unroll
                for (int mi = 0; mi < 2; mi++)
                    #pragma unroll
                    for (int j = 0; j < 8; j++)
                        mma16816(acc[mi][j], af[mi], bf[j]);
            }
        }
        __syncthreads();
    }

    #pragma unroll
    for (int mi = 0; mi < 2; mi++)
        #pragma unroll
        for (int j = 0; j < 8; j++) {
            int r = wm*32 + mi*16 + (lane >> 2);
            int c = wn*64 + j*8 + (lane & 3)*2;
            Ss[r*132 + c]         = acc[mi][j][0];
            Ss[r*132 + c + 1]     = acc[mi][j][1];
            Ss[(r+8)*132 + c]     = acc[mi][j][2];
            Ss[(r+8)*132 + c + 1] = acc[mi][j][3];
        }
    __syncthreads();

    #pragma unroll 1
    for (int rr = 0; rr < 16; rr++) {
        int r = wid*16 + rr;
        float a0 = Ss[r*132 + lane],      a1 = Ss[r*132 + lane + 32];
        float a2 = Ss[r*132 + lane + 64], a3 = Ss[r*132 + lane + 96];
        float ss = a0*a0 + a1*a1 + a2*a2 + a3*a3;
        #pragma unroll
        for (int o = 16; o > 0; o >>= 1) ss += __shfl_xor_sync(0xffffffffu, ss, o);
        float inv1 = rsqrtf(fmaxf(ss, 1e-12f));
        const float* vrow = g_V + ((size_t)b*Mm + m0 + r)*DOUT;
        float t0 = vrow[lane]      + a0*inv1;
        float t1 = vrow[lane + 32] + a1*inv1;
        float t2 = vrow[lane + 64] + a2*inv1;
        float t3 = vrow[lane + 96] + a3*inv1;
        float ss2 = t0*t0 + t1*t1 + t2*t2 + t3*t3;
        #pragma unroll
        for (int o = 16; o > 0; o >>= 1) ss2 += __shfl_xor_sync(0xffffffffu, ss2, o);
        float inv2 = rsqrtf(fmaxf(ss2, 1e-12f));
        float* orow = out + ((size_t)b*Mm + m0 + r)*DOUT;
        orow[lane]      = t0*inv2;
        orow[lane + 32] = t1*inv2;
        orow[lane + 64] = t2*inv2;
        orow[lane + 96] = t3*inv2;
    }
}

// ---------------------------------------------------------------------------
extern "C" void kernel_launch(void* const* d_in, const int* in_sizes, int n_in,
                              void* d_out, int out_size)
{
    const float* Y   = (const float*)d_in[0];
    const int*   idx = (const int*)  d_in[1];
    const float* Wq  = (const float*)d_in[2];
    const float* bq  = (const float*)d_in[3];
    const float* Wk  = (const float*)d_in[4];
    const float* bk  = (const float*)d_in[5];
    const float* Wv  = (const float*)d_in[6];
    const float* bv  = (const float*)d_in[7];

    float* out = (float*)d_out;                       // [8,2048,128]
    float* att = out + (size_t)Bb*Mm*DOUT;            // [8,2048,2048]

    const int smemP = 208896;
    const int smemG = 4 * 128 * PITB;                 // 139264

    cudaFuncSetAttribute(projmma_kernel, cudaFuncAttributeMaxDynamicSharedMemorySize, smemP);
    cudaFuncSetAttribute(attnA_kernel,   cudaFuncAttributeMaxDynamicSharedMemorySize, smemG);
    cudaFuncSetAttribute(attnC_kernel,   cudaFuncAttributeMaxDynamicSharedMemorySize, smemG);

    prep_kernel<<<3, 256>>>(Wq, Wk, Wv);
    projmma_kernel<<<(Bb*Mm)/128, 256, smemP>>>(Y, idx, bq, bk, bv);
    attnA_kernel<<<dim3(Mm/128, Bb), 256, smemG>>>(att);
    attnC_kernel<<<dim3(Mm/128, Bb), 256, smemG>>>(att, out);
}

// round 6
// speedup vs baseline: 3.6849x; 1.1822x over previous
#include <cuda_runtime.h>
#include <cuda_bf16.h>
#include <cstdint>

#define Bb   8
#define Nn   4096
#define Mm   2048
#define DIN  256
#define DOUT 128

__device__ __nv_bfloat16 g_Qh [Bb*Mm*DOUT];
__device__ __nv_bfloat16 g_Ql [Bb*Mm*DOUT];
__device__ __nv_bfloat16 g_Kh [Bb*Mm*DOUT];
__device__ __nv_bfloat16 g_Kl [Bb*Mm*DOUT];
__device__ float         g_V  [Bb*Mm*DOUT];
__device__ __nv_bfloat16 g_Vth[Bb*DOUT*Mm];    // [b][e][m]
__device__ __nv_bfloat16 g_Vtl[Bb*DOUT*Mm];
__device__ __nv_bfloat16 g_Wth[3*DOUT*DIN];    // [wsel][n][k]
__device__ __nv_bfloat16 g_Wtl[3*DOUT*DIN];
__device__ __nv_bfloat16 g_Ah [(size_t)Bb*Mm*Mm];  // att bf16 hi
__device__ __nv_bfloat16 g_Al [(size_t)Bb*Mm*Mm];  // att bf16 lo

// ---------------- helpers ----------------
__device__ __forceinline__ uint32_t cvta_smem(const void* p) {
    uint32_t a;
    asm("{ .reg .u64 t; cvta.to.shared.u64 t, %1; cvt.u32.u64 %0, t; }" : "=r"(a) : "l"(p));
    return a;
}
__device__ __forceinline__ uint32_t b2pack(float a, float b) {
    uint16_t la = __bfloat16_as_ushort(__float2bfloat16(a));
    uint16_t lb = __bfloat16_as_ushort(__float2bfloat16(b));
    return (uint32_t)la | ((uint32_t)lb << 16);
}
__device__ __forceinline__ float bhi(float x) {
    return __bfloat162float(__float2bfloat16(x));
}
__device__ __forceinline__ void ldmA(uint32_t a[4], uint32_t addr) {
    asm volatile("ldmatrix.sync.aligned.m8n8.x4.shared.b16 {%0,%1,%2,%3}, [%4];"
        : "=r"(a[0]),"=r"(a[1]),"=r"(a[2]),"=r"(a[3]) : "r"(addr));
}
__device__ __forceinline__ void ldmB(uint32_t b[2], uint32_t addr) {
    asm volatile("ldmatrix.sync.aligned.m8n8.x2.shared.b16 {%0,%1}, [%2];"
        : "=r"(b[0]),"=r"(b[1]) : "r"(addr));
}
__device__ __forceinline__ void mma16816(float c[4], const uint32_t a[4], const uint32_t b[2]) {
    asm volatile("mma.sync.aligned.m16n8k16.row.col.f32.bf16.bf16.f32 "
        "{%0,%1,%2,%3}, {%4,%5,%6,%7}, {%8,%9}, {%0,%1,%2,%3};"
        : "+f"(c[0]),"+f"(c[1]),"+f"(c[2]),"+f"(c[3])
        : "r"(a[0]),"r"(a[1]),"r"(a[2]),"r"(a[3]), "r"(b[0]),"r"(b[1]));
}
#define CPA(d, s) asm volatile("cp.async.cg.shared.global [%0], [%1], 16;" :: "r"(d), "l"(s))
#define CPC()     asm volatile("cp.async.commit_group;" ::: "memory")
#define CPW1()    asm volatile("cp.async.wait_group 1;" ::: "memory")
#define CPW0()    asm volatile("cp.async.wait_group 0;" ::: "memory")

#define PIT 136
#define PITB 272
#define P64B 144

// ---------------------------------------------------------------------------
// prep: W[k][n] fp32 -> W^T[n][k] bf16 hi/lo (3 matrices).
// ---------------------------------------------------------------------------
__global__ void prep_kernel(const float* __restrict__ Wq,
                            const float* __restrict__ Wk,
                            const float* __restrict__ Wv)
{
    const float* W = (blockIdx.x == 0) ? Wq : (blockIdx.x == 1) ? Wk : Wv;
    __nv_bfloat16* dh = g_Wth + blockIdx.x * DOUT * DIN;
    __nv_bfloat16* dl = g_Wtl + blockIdx.x * DOUT * DIN;
    for (int i = threadIdx.x; i < DOUT * (DIN/2); i += 256) {
        int n = i >> 7, k = (i & 127) * 2;
        float x0 = W[(size_t)k*DOUT + n];
        float x1 = W[(size_t)(k+1)*DOUT + n];
        *reinterpret_cast<uint32_t*>(dh + (size_t)n*DIN + k) = b2pack(x0, x1);
        *reinterpret_cast<uint32_t*>(dl + (size_t)n*DIN + k) =
            b2pack(x0 - bhi(x0), x1 - bhi(x1));
    }
}

// ---------------------------------------------------------------------------
// projmma: gather + Q/K/V projections via split-bf16 mma.sync. (round-5 proven)
// ---------------------------------------------------------------------------
__global__ __launch_bounds__(256, 1)
void projmma_kernel(const float* __restrict__ Y, const int* __restrict__ idx,
                    const float* __restrict__ bq, const float* __restrict__ bk,
                    const float* __restrict__ bv)
{
    extern __shared__ char smraw[];
    char* Ah = smraw;
    char* Al = smraw + 69632;
    char* Bh = smraw + 139264;
    char* Bl = smraw + 174080;
    float* Vs = reinterpret_cast<float*>(Bh);
    __shared__ int idxs[128];

    const int tid = threadIdx.x, lane = tid & 31, wid = tid >> 5;
    const int wm = wid >> 1, wn = wid & 1;
    const int row0 = blockIdx.x * 128;
    const int b    = row0 / Mm;
    const int m0   = row0 % Mm;

    if (tid < 128) idxs[tid] = idx[b*Mm + m0 + tid];
    __syncthreads();

    for (int i = tid; i < 128*64; i += 256) {
        int row = i >> 6, c4 = i & 63;
        float4 y = *reinterpret_cast<const float4*>(
            Y + ((size_t)b*Nn + idxs[row])*DIN + c4*4);
        int kc = c4 >> 5;
        uint32_t off = (uint32_t)(kc*34816 + row*PITB + (c4 & 31)*8);
        *reinterpret_cast<uint2*>(Ah + off) =
            make_uint2(b2pack(y.x, y.y), b2pack(y.z, y.w));
        *reinterpret_cast<uint2*>(Al + off) =
            make_uint2(b2pack(y.x-bhi(y.x), y.y-bhi(y.y)),
                       b2pack(y.z-bhi(y.z), y.w-bhi(y.w)));
    }

    const uint32_t sAh = cvta_smem(Ah), sAl = cvta_smem(Al);
    const uint32_t sBh = cvta_smem(Bh), sBl = cvta_smem(Bl);

    const int aRow = wm*32 + (lane & 15);
    const int aKb  = (lane >> 4) * 8;
    const int bRow = wn*64 + (lane & 7);
    const int bKb  = ((lane >> 3) & 1) * 8;

    #pragma unroll 1
    for (int wsel = 0; wsel < 3; wsel++) {
        float acc[2][8][4] = {};
        #pragma unroll 1
        for (int kc = 0; kc < 2; kc++) {
            __syncthreads();
            const __nv_bfloat16* wh = g_Wth + (size_t)wsel*DOUT*DIN + kc*128;
            const __nv_bfloat16* wl = g_Wtl + (size_t)wsel*DOUT*DIN + kc*128;
            for (int i = tid; i < 128*16; i += 256) {
                int n = i >> 4, c8 = i & 15;
                uint32_t off = (uint32_t)(n*PITB + c8*16);
                size_t go = (size_t)n*DIN + c8*8;
                *reinterpret_cast<uint4*>(Bh + off) =
                    *reinterpret_cast<const uint4*>(wh + go);
                *reinterpret_cast<uint4*>(Bl + off) =
                    *reinterpret_cast<const uint4*>(wl + go);
            }
            __syncthreads();
            uint32_t aBase = kc * 34816;
            #pragma unroll
            for (int term = 0; term < 3; term++) {
                uint32_t sA = ((term == 2) ? sAl : sAh) + aBase;
                uint32_t sB = (term == 1) ? sBl : sBh;
                #pragma unroll
                for (int ks = 0; ks < 8; ks++) {
                    uint32_t af[2][4], bf[8][2];
                    #pragma unroll
                    for (int mi = 0; mi < 2; mi++)
                        ldmA(af[mi], sA + ((aRow + mi*16)*PIT + aKb + ks*16)*2);
                    #pragma unroll
                    for (int j = 0; j < 8; j++)
                        ldmB(bf[j], sB + ((bRow + j*8)*PIT + bKb + ks*16)*2);
                    #pragma unroll
                    for (int mi = 0; mi < 2; mi++)
                        #pragma unroll
                        for (int j = 0; j < 8; j++)
                            mma16816(acc[mi][j], af[mi], bf[j]);
                }
            }
        }

        const float* bp = (wsel == 0) ? bq : (wsel == 1) ? bk : bv;
        float bias2[8][2];
        #pragma unroll
        for (int j = 0; j < 8; j++) {
            int c = wn*64 + j*8 + (lane & 3)*2;
            bias2[j][0] = bp[c]; bias2[j][1] = bp[c+1];
        }

        if (wsel < 2) {
            const float s = (wsel == 0) ? 0.0625f : 1.0f;
            __nv_bfloat16* gh = (wsel == 0) ? g_Qh : g_Kh;
            __nv_bfloat16* gl = (wsel == 0) ? g_Ql : g_Kl;
            #pragma unroll
            for (int mi = 0; mi < 2; mi++)
                #pragma unroll
                for (int j = 0; j < 8; j++) {
                    int r = wm*32 + mi*16 + (lane >> 2);
                    int c = wn*64 + j*8 + (lane & 3)*2;
                    float q0 = (acc[mi][j][0] + bias2[j][0]) * s;
                    float q1 = (acc[mi][j][1] + bias2[j][1]) * s;
                    float q2 = (acc[mi][j][2] + bias2[j][0]) * s;
                    float q3 = (acc[mi][j][3] + bias2[j][1]) * s;
                    size_t o0 = ((size_t)(b*Mm + m0 + r))*DOUT + c;
                    size_t o1 = ((size_t)(b*Mm + m0 + r + 8))*DOUT + c;
                    *reinterpret_cast<uint32_t*>(gh + o0) = b2pack(q0, q1);
                    *reinterpret_cast<uint32_t*>(gl + o0) =
                        b2pack(q0 - bhi(q0), q1 - bhi(q1));
                    *reinterpret_cast<uint32_t*>(gh + o1) = b2pack(q2, q3);
                    *reinterpret_cast<uint32_t*>(gl + o1) =
                        b2pack(q2 - bhi(q2), q3 - bhi(q3));
                }
        } else {
            __syncthreads();
            #pragma unroll
            for (int mi = 0; mi < 2; mi++)
                #pragma unroll
                for (int j = 0; j < 8; j++) {
                    int r = wm*32 + mi*16 + (lane >> 2);
                    int c = wn*64 + j*8 + (lane & 3)*2;
                    float v0 = fmaxf(acc[mi][j][0] + bias2[j][0], 0.f);
                    float v1 = fmaxf(acc[mi][j][1] + bias2[j][1], 0.f);
                    float v2 = fmaxf(acc[mi][j][2] + bias2[j][0], 0.f);
                    float v3 = fmaxf(acc[mi][j][3] + bias2[j][1], 0.f);
                    *reinterpret_cast<float2*>(
                        g_V + ((size_t)(b*Mm + m0 + r))*DOUT + c) = make_float2(v0, v1);
                    *reinterpret_cast<float2*>(
                        g_V + ((size_t)(b*Mm + m0 + r + 8))*DOUT + c) = make_float2(v2, v3);
                    Vs[r*132 + c]       = v0;
                    Vs[r*132 + c + 1]   = v1;
                    Vs[(r+8)*132 + c]   = v2;
                    Vs[(r+8)*132 + c+1] = v3;
                }
            __syncthreads();
            int e = tid & 127, half = tid >> 7;
            #pragma unroll
            for (int seg = 0; seg < 2; seg++) {
                int mb = half*64 + seg*32;
                uint32_t hp[16], lp[16];
                #pragma unroll
                for (int t = 0; t < 16; t++) {
                    float x0 = Vs[(mb + 2*t    )*132 + e];
                    float x1 = Vs[(mb + 2*t + 1)*132 + e];
                    hp[t] = b2pack(x0, x1);
                    lp[t] = b2pack(x0 - bhi(x0), x1 - bhi(x1));
                }
                uint4* dh = reinterpret_cast<uint4*>(
                    g_Vth + ((size_t)b*DOUT + e)*Mm + m0 + mb);
                uint4* dl = reinterpret_cast<uint4*>(
                    g_Vtl + ((size_t)b*DOUT + e)*Mm + m0 + mb);
                #pragma unroll
                for (int q = 0; q < 4; q++) {
                    dh[q] = make_uint4(hp[4*q],hp[4*q+1],hp[4*q+2],hp[4*q+3]);
                    dl[q] = make_uint4(lp[4*q],lp[4*q+1],lp[4*q+2],lp[4*q+3]);
                }
            }
        }
    }
}

// ---------------------------------------------------------------------------
// Kernel A: S = (Q/16) K^T, cp.async ping-pong over 32 key-chunks of 64.
// Direct S stores; softmax writes att fp32 + bf16 hi/lo split (g_Ah/g_Al).
// smem: Qh 34816 | Ql 34816 | Kbuf0 34816 | Kbuf1 34816 = 139264.
// ---------------------------------------------------------------------------
__global__ __launch_bounds__(256, 1)
void attnA_kernel(float* __restrict__ att)
{
    extern __shared__ char smraw[];
    const int tid = threadIdx.x, lane = tid & 31, wid = tid >> 5;
    const int b = blockIdx.y, m0 = blockIdx.x * 128;
    const int wm = wid >> 1, wn = wid & 1;

    char* Qh = smraw;
    char* Ql = smraw + 34816;
    char* Kb = smraw + 69632;            // 2 bufs x (Kh 17408 + Kl 17408)
    const uint32_t sQh = cvta_smem(Qh), sQl = cvta_smem(Ql);
    const uint32_t sKb = cvta_smem(Kb);

    // async fill of K chunk ch into buf
    auto issueK = [&](int ch, int buf) {
        const uint32_t dbase = sKb + buf*34816;
        #pragma unroll
        for (int t = 0; t < 8; t++) {
            int i = tid + t*256;
            int tile = i >> 10, row = (i >> 4) & 63, p = i & 15;
            const __nv_bfloat16* src = (tile ? g_Kl : g_Kh)
                + ((size_t)(b*Mm + ch*64 + row))*DOUT + p*8;
            CPA(dbase + tile*17408 + row*PITB + p*16, src);
        }
        CPC();
    };

    issueK(0, 0);

    // Q hi/lo resident
    {
        const uint4* qh = reinterpret_cast<const uint4*>(g_Qh + ((size_t)b*Mm + m0)*DOUT);
        const uint4* ql = reinterpret_cast<const uint4*>(g_Ql + ((size_t)b*Mm + m0)*DOUT);
        for (int i = tid; i < 128*16; i += 256) {
            int row = i >> 4, c8 = i & 15;
            *reinterpret_cast<uint4*>(Qh + row*PITB + c8*16) = qh[i];
            *reinterpret_cast<uint4*>(Ql + row*PITB + c8*16) = ql[i];
        }
    }

    const int aRow = wm*32 + (lane & 15);
    const int aKb  = (lane >> 4) * 8;
    const int bRow = wn*32 + (lane & 7);
    const int bKb  = ((lane >> 3) & 1) * 8;

    #pragma unroll 1
    for (int ch = 0; ch < 32; ch++) {
        if (ch < 31) issueK(ch + 1, (ch + 1) & 1);
        if (ch < 31) { CPW1(); } else { CPW0(); }
        __syncthreads();

        const uint32_t kh = sKb + (ch & 1)*34816;
        const uint32_t kl = kh + 17408;

        float acc[2][4][4] = {};
        #pragma unroll
        for (int term = 0; term < 3; term++) {
            uint32_t sA = (term == 2) ? sQl : sQh;
            uint32_t sB = (term == 1) ? kl : kh;
            #pragma unroll
            for (int ks = 0; ks < 8; ks++) {
                uint32_t af[2][4], bf[4][2];
                #pragma unroll
                for (int mi = 0; mi < 2; mi++)
                    ldmA(af[mi], sA + ((aRow + mi*16)*PIT + aKb + ks*16)*2);
                #pragma unroll
                for (int j = 0; j < 4; j++)
                    ldmB(bf[j], sB + (bRow + j*8)*PITB + (bKb + ks*16)*2);
                #pragma unroll
                for (int mi = 0; mi < 2; mi++)
                    #pragma unroll
                    for (int j = 0; j < 4; j++)
                        mma16816(acc[mi][j], af[mi], bf[j]);
            }
        }
        __syncthreads();   // smem K consumption done; next issue may overwrite

        // direct S store
        #pragma unroll
        for (int mi = 0; mi < 2; mi++)
            #pragma unroll
            for (int j = 0; j < 4; j++) {
                int r = wm*32 + mi*16 + (lane >> 2);
                int c = ch*64 + wn*32 + j*8 + (lane & 3)*2;
                *reinterpret_cast<float2*>(
                    att + ((size_t)(b*Mm + m0 + r))*Mm + c) =
                    make_float2(acc[mi][j][0], acc[mi][j][1]);
                *reinterpret_cast<float2*>(
                    att + ((size_t)(b*Mm + m0 + r + 8))*Mm + c) =
                    make_float2(acc[mi][j][2], acc[mi][j][3]);
            }
    }
    __syncthreads();

    // softmax: warp wid owns rows [wid*16, wid*16+16); emits fp32 + bf16 split
    #pragma unroll 1
    for (int rr = 0; rr < 16; rr++) {
        size_t rowi = (size_t)(b*Mm + m0 + wid*16 + rr);
        float* row = att + rowi*Mm;
        float4 v[16];
        #pragma unroll
        for (int j = 0; j < 16; j++) v[j] = reinterpret_cast<float4*>(row)[lane + j*32];
        float mx = -1e30f;
        #pragma unroll
        for (int j = 0; j < 16; j++)
            mx = fmaxf(mx, fmaxf(fmaxf(v[j].x, v[j].y), fmaxf(v[j].z, v[j].w)));
        #pragma unroll
        for (int o = 16; o > 0; o >>= 1) mx = fmaxf(mx, __shfl_xor_sync(0xffffffffu, mx, o));
        float sum = 0.f;
        #pragma unroll
        for (int j = 0; j < 16; j++) {
            v[j].x = __expf(v[j].x - mx); v[j].y = __expf(v[j].y - mx);
            v[j].z = __expf(v[j].z - mx); v[j].w = __expf(v[j].w - mx);
            sum += (v[j].x + v[j].y) + (v[j].z + v[j].w);
        }
        #pragma unroll
        for (int o = 16; o > 0; o >>= 1) sum += __shfl_xor_sync(0xffffffffu, sum, o);
        float inv = 1.f / sum;
        uint2* ah = reinterpret_cast<uint2*>(g_Ah + rowi*Mm);
        uint2* al = reinterpret_cast<uint2*>(g_Al + rowi*Mm);
        #pragma unroll
        for (int j = 0; j < 16; j++) {
            v[j].x *= inv; v[j].y *= inv; v[j].z *= inv; v[j].w *= inv;
            reinterpret_cast<float4*>(row)[lane + j*32] = v[j];
            ah[lane + j*32] = make_uint2(b2pack(v[j].x, v[j].y), b2pack(v[j].z, v[j].w));
            al[lane + j*32] = make_uint2(
                b2pack(v[j].x - bhi(v[j].x), v[j].y - bhi(v[j].y)),
                b2pack(v[j].z - bhi(v[j].z), v[j].w - bhi(v[j].w)));
        }
    }
}

// ---------------------------------------------------------------------------
// Kernel C: AV = att @ V, cp.async ping-pong over 32 key-chunks of 64;
// A tiles from g_Ah/g_Al (pre-split), B from g_Vth/g_Vtl. l2norm epilogue.
// smem: 2 bufs x (Ah|Al|Bh|Bl each 128 x 144B = 18432) = 147456.
// ---------------------------------------------------------------------------
__global__ __launch_bounds__(256, 1)
void attnC_kernel(float* __restrict__ out)
{
    extern __shared__ char smraw[];
    const int tid = threadIdx.x, lane = tid & 31, wid = tid >> 5;
    const int b = blockIdx.y, m0 = blockIdx.x * 128;
    const int wm = wid >> 1, wn = wid & 1;

    const uint32_t sb = cvta_smem(smraw);

    auto issueC = [&](int ch, int buf) {
        const uint32_t dbase = sb + buf*73728;
        #pragma unroll
        for (int t = 0; t < 16; t++) {
            int i = tid + t*256;
            int tile = i >> 10, row = (i >> 3) & 127, p = i & 7;
            const __nv_bfloat16* src;
            if (tile == 0)
                src = g_Ah + ((size_t)(b*Mm + m0 + row))*Mm + ch*64 + p*8;
            else if (tile == 1)
                src = g_Al + ((size_t)(b*Mm + m0 + row))*Mm + ch*64 + p*8;
            else if (tile == 2)
                src = g_Vth + ((size_t)(b*DOUT + row))*Mm + ch*64 + p*8;
            else
                src = g_Vtl + ((size_t)(b*DOUT + row))*Mm + ch*64 + p*8;
            CPA(dbase + tile*18432 + row*P64B + p*16, src);
        }
        CPC();
    };

    issueC(0, 0);

    const int aRow = wm*32 + (lane & 15);
    const int aKb  = (lane >> 4) * 8;
    const int bRow = wn*64 + (lane & 7);
    const int bKb  = ((lane >> 3) & 1) * 8;

    float acc[2][8][4] = {};

    #pragma unroll 1
    for (int ch = 0; ch < 32; ch++) {
        if (ch < 31) issueC(ch + 1, (ch + 1) & 1);
        if (ch < 31) { CPW1(); } else { CPW0(); }
        __syncthreads();

        const uint32_t base = sb + (ch & 1)*73728;
        const uint32_t tAh = base, tAl = base + 18432;
        const uint32_t tBh = base + 36864, tBl = base + 55296;

        #pragma unroll
        for (int term = 0; term < 3; term++) {
            uint32_t sA = (term == 2) ? tAl : tAh;
            uint32_t sB = (term == 1) ? tBl : tBh;
            #pragma unroll
            for (int ks = 0; ks < 4; ks++) {
                uint32_t af[2][4], bf[8][2];
                #pragma unroll
                for (int mi = 0; mi < 2; mi++)
                    ldmA(af[mi], sA + (aRow + mi*16)*P64B + (aKb + ks*16)*2);
                #pragma unroll
                for (int j = 0; j < 8; j++)
                    ldmB(bf[j], sB + (bRow + j*8)*P64B + (bKb + ks*16)*2);
                #pragma unroll
                for (int mi = 0; mi < 2; mi++)
                    #pragma unroll
                    for (int j = 0; j < 8; j++)
                        mma16816(acc[mi][j], af[mi], bf[j]);
            }
        }
        __syncthreads();
    }

    // park AV in smem (alias buf0) for the row-wise epilogue
    float* Ss = reinterpret_cast<float*>(smraw);
    #pragma unroll
    for (int mi = 0; mi < 2; mi++)
        #pragma unroll
        for (int j = 0; j < 8; j++) {
            int r = wm*32 + mi*16 + (lane >> 2);
            int c = wn*64 + j*8 + (lane & 3)*2;
            Ss[r*132 + c]         = acc[mi][j][0];
            Ss[r*132 + c + 1]     = acc[mi][j][1];
            Ss[(r+8)*132 + c]     = acc[mi][j][2];
            Ss[(r+8)*132 + c + 1] = acc[mi][j][3];
        }
    __syncthreads();

    #pragma unroll 1
    for (int rr = 0; rr < 16; rr++) {
        int r = wid*16 + rr;
        float a0 = Ss[r*132 + lane],      a1 = Ss[r*132 + lane + 32];
        float a2 = Ss[r*132 + lane + 64], a3 = Ss[r*132 + lane + 96];
        float ss = a0*a0 + a1*a1 + a2*a2 + a3*a3;
        #pragma unroll
        for (int o = 16; o > 0; o >>= 1) ss += __shfl_xor_sync(0xffffffffu, ss, o);
        float inv1 = rsqrtf(fmaxf(ss, 1e-12f));
        const float* vrow = g_V + ((size_t)b*Mm + m0 + r)*DOUT;
        float t0 = vrow[lane]      + a0*inv1;
        float t1 = vrow[lane + 32] + a1*inv1;
        float t2 = vrow[lane + 64] + a2*inv1;
        float t3 = vrow[lane + 96] + a3*inv1;
        float ss2 = t0*t0 + t1*t1 + t2*t2 + t3*t3;
        #pragma unroll
        for (int o = 16; o > 0; o >>= 1) ss2 += __shfl_xor_sync(0xffffffffu, ss2, o);
        float inv2 = rsqrtf(fmaxf(ss2, 1e-12f));
        float* orow = out + ((size_t)b*Mm + m0 + r)*DOUT;
        orow[lane]      = t0*inv2;
        orow[lane + 32] = t1*inv2;
        orow[lane + 64] = t2*inv2;
        orow[lane + 96] = t3*inv2;
    }
}

// ---------------------------------------------------------------------------
extern "C" void kernel_launch(void* const* d_in, const int* in_sizes, int n_in,
                              void* d_out, int out_size)
{
    const float* Y   = (const float*)d_in[0];
    const int*   idx = (const int*)  d_in[1];
    const float* Wq  = (const float*)d_in[2];
    const float* bq  = (const float*)d_in[3];
    const float* Wk  = (const float*)d_in[4];
    const float* bk  = (const float*)d_in[5];
    const float* Wv  = (const float*)d_in[6];
    const float* bv  = (const float*)d_in[7];

    float* out = (float*)d_out;                       // [8,2048,128]
    float* att = out + (size_t)Bb*Mm*DOUT;            // [8,2048,2048]

    const int smemP = 208896;
    const int smemA = 139264;
    const int smemC = 147456;

    cudaFuncSetAttribute(projmma_kernel, cudaFuncAttributeMaxDynamicSharedMemorySize, smemP);
    cudaFuncSetAttribute(attnA_kernel,   cudaFuncAttributeMaxDynamicSharedMemorySize, smemA);
    cudaFuncSetAttribute(attnC_kernel,   cudaFuncAttributeMaxDynamicSharedMemorySize, smemC);

    prep_kernel<<<3, 256>>>(Wq, Wk, Wv);
    projmma_kernel<<<(Bb*Mm)/128, 256, smemP>>>(Y, idx, bq, bk, bv);
    attnA_kernel<<<dim3(Mm/128, Bb), 256, smemA>>>(att);
    attnC_kernel<<<dim3(Mm/128, Bb), 256, smemC>>>(out);
}